// round 1
// baseline (speedup 1.0000x reference)
#include <cuda_runtime.h>

#define S_LEN  2048
#define BATCH  2
#define DMODEL 1024
#define NHEAD  16
#define HDIM   64
#define MTOT   (BATCH * S_LEN)   // 4096

// ---------------- scratch (allocation-free: device globals) ----------------
__device__ float g_q[(size_t)MTOT * DMODEL];   // [B,H,S,Hd] head-split
__device__ float g_k[(size_t)MTOT * DMODEL];
__device__ float g_v[(size_t)MTOT * DMODEL];
__device__ float g_ctx[(size_t)MTOT * DMODEL]; // [B,S,D]

// ---------------- SGEMM core: 128x128x8, 256 threads, 8x8/thread ----------
template<bool SPLIT_HEADS>
__device__ __forceinline__ void gemm_body(const float* __restrict__ A,
                                          const float* __restrict__ W,
                                          const float* __restrict__ bias,
                                          float* __restrict__ C)
{
    constexpr int BM = 128, BN = 128, BK = 8;
    constexpr int K = DMODEL, N = DMODEL;
    __shared__ float As[BK][BM];
    __shared__ float Bs[BK][BN];

    const int tid = threadIdx.x;
    const int m0 = blockIdx.y * BM;
    const int n0 = blockIdx.x * BN;
    const int tm = tid / 16;          // 0..15
    const int tn = tid % 16;          // 0..15

    float acc[8][8];
    #pragma unroll
    for (int i = 0; i < 8; i++)
        #pragma unroll
        for (int j = 0; j < 8; j++) acc[i][j] = 0.0f;

    const int arow = tid >> 1;          // 0..127
    const int acol = (tid & 1) * 4;     // 0 or 4
    const int brow = tid >> 5;          // 0..7
    const int bcol = (tid & 31) * 4;    // 0..124

    const float* Aptr = A + (size_t)(m0 + arow) * K + acol;
    const float* Wptr = W + (size_t)brow * N + n0 + bcol;

    for (int k0 = 0; k0 < K; k0 += BK) {
        float4 av = *(const float4*)Aptr;  Aptr += BK;
        float4 bv = *(const float4*)Wptr;  Wptr += (size_t)BK * N;
        As[acol + 0][arow] = av.x;
        As[acol + 1][arow] = av.y;
        As[acol + 2][arow] = av.z;
        As[acol + 3][arow] = av.w;
        *(float4*)&Bs[brow][bcol] = bv;
        __syncthreads();

        #pragma unroll
        for (int kk = 0; kk < BK; kk++) {
            float a[8], b[8];
            *(float4*)(a)     = *(const float4*)&As[kk][tm * 8];
            *(float4*)(a + 4) = *(const float4*)&As[kk][tm * 8 + 4];
            *(float4*)(b)     = *(const float4*)&Bs[kk][tn * 8];
            *(float4*)(b + 4) = *(const float4*)&Bs[kk][tn * 8 + 4];
            #pragma unroll
            for (int i = 0; i < 8; i++)
                #pragma unroll
                for (int j = 0; j < 8; j++)
                    acc[i][j] = fmaf(a[i], b[j], acc[i][j]);
        }
        __syncthreads();
    }

    // epilogue: + bias, optional head-split store
    #pragma unroll
    for (int i = 0; i < 8; i++) {
        const int m = m0 + tm * 8 + i;
        #pragma unroll
        for (int j = 0; j < 8; j += 4) {
            const int n = n0 + tn * 8 + j;
            float4 o;
            o.x = acc[i][j + 0] + bias[n + 0];
            o.y = acc[i][j + 1] + bias[n + 1];
            o.z = acc[i][j + 2] + bias[n + 2];
            o.w = acc[i][j + 3] + bias[n + 3];
            if (SPLIT_HEADS) {
                const int b  = m / S_LEN, s  = m % S_LEN;
                const int h  = n / HDIM,  hd = n % HDIM;  // n..n+3 same head (HDIM=64, n%4==0)
                float* out = C + (((size_t)(b * NHEAD + h) * S_LEN + s) * HDIM + hd);
                *(float4*)out = o;
            } else {
                *(float4*)(C + (size_t)m * N + n) = o;
            }
        }
    }
}

__global__ void __launch_bounds__(256)
gemm_qkv_kernel(const float* __restrict__ x,
                const float* __restrict__ wq, const float* __restrict__ bq,
                const float* __restrict__ wk, const float* __restrict__ bk,
                const float* __restrict__ wv, const float* __restrict__ bv)
{
    const float* W; const float* bias; float* C;
    if (blockIdx.z == 0)      { W = wq; bias = bq; C = g_q; }
    else if (blockIdx.z == 1) { W = wk; bias = bk; C = g_k; }
    else                      { W = wv; bias = bv; C = g_v; }
    gemm_body<true>(x, W, bias, C);
}

__global__ void __launch_bounds__(256)
gemm_out_kernel(const float* __restrict__ wo, const float* __restrict__ bo,
                float* __restrict__ out)
{
    gemm_body<false>(g_ctx, wo, bo, out);
}

// ---------------- flash attention (fp32, 64-query tile) --------------------
// smem layouts (XOR-swizzled at float4-chunk granularity, 48KB total):
//   Qt[d][row]  : transposed Q tile, conflict-free float4 reads in phase 1
//   Kt[d][key]  : transposed K tile; aliased as Pt[key][row] for phase 2
//   Vs[key][d]  : natural V tile
#define SWZ(dim, r) ((dim) * 64 + ((((r) >> 2) ^ ((dim) & 15)) << 2) + ((r) & 3))

__global__ void __launch_bounds__(256)
flash_attn_kernel(void)
{
    __shared__ float Qt[64 * 64];
    __shared__ float Kt[64 * 64];   // also used as Pt
    __shared__ float Vs[64][64];

    const int tid = threadIdx.x;
    const int tx  = tid & 15;       // 0..15 : key-cols (phase1) / dims (phase2)
    const int ty  = tid >> 4;       // 0..15 : query rows
    const int bh  = blockIdx.y;     // b*NHEAD + h
    const int qb  = blockIdx.x;     // query block

    const float* qbase = g_q + (size_t)bh * S_LEN * HDIM + (size_t)qb * 64 * HDIM;
    const float* kbase = g_k + (size_t)bh * S_LEN * HDIM;
    const float* vbase = g_v + (size_t)bh * S_LEN * HDIM;

    // load Q tile transposed+swizzled
    #pragma unroll
    for (int c = 0; c < 4; c++) {
        const int lin = c * 1024 + tid * 4;
        const int row = lin >> 6, d0 = lin & 63;
        float4 qv = *(const float4*)(qbase + row * HDIM + d0);
        Qt[SWZ(d0 + 0, row)] = qv.x;
        Qt[SWZ(d0 + 1, row)] = qv.y;
        Qt[SWZ(d0 + 2, row)] = qv.z;
        Qt[SWZ(d0 + 3, row)] = qv.w;
    }

    float m_i[4], l_i[4], acc[4][4];
    #pragma unroll
    for (int i = 0; i < 4; i++) {
        m_i[i] = -1e30f; l_i[i] = 0.0f;
        #pragma unroll
        for (int j = 0; j < 4; j++) acc[i][j] = 0.0f;
    }

    for (int kb = 0; kb < S_LEN / 64; kb++) {
        __syncthreads();   // previous phase-2 reads of Kt(=Pt)/Vs are done
        const float* kp = kbase + (size_t)kb * 64 * HDIM;
        const float* vp = vbase + (size_t)kb * 64 * HDIM;
        #pragma unroll
        for (int c = 0; c < 4; c++) {
            const int lin = c * 1024 + tid * 4;
            const int row = lin >> 6, d0 = lin & 63;
            float4 kv = *(const float4*)(kp + row * HDIM + d0);
            Kt[SWZ(d0 + 0, row)] = kv.x;
            Kt[SWZ(d0 + 1, row)] = kv.y;
            Kt[SWZ(d0 + 2, row)] = kv.z;
            Kt[SWZ(d0 + 3, row)] = kv.w;
            *(float4*)&Vs[row][d0] = *(const float4*)(vp + row * HDIM + d0);
        }
        __syncthreads();

        // ---- phase 1: S = Q K^T * scale
        float s[4][4];
        #pragma unroll
        for (int i = 0; i < 4; i++)
            #pragma unroll
            for (int j = 0; j < 4; j++) s[i][j] = 0.0f;

        #pragma unroll 16
        for (int d = 0; d < HDIM; d++) {
            float qv[4], kv[4];
            *(float4*)qv = *(const float4*)&Qt[SWZ(d, ty * 4)];
            *(float4*)kv = *(const float4*)&Kt[SWZ(d, tx * 4)];
            #pragma unroll
            for (int i = 0; i < 4; i++)
                #pragma unroll
                for (int j = 0; j < 4; j++)
                    s[i][j] = fmaf(qv[i], kv[j], s[i][j]);
        }

        // ---- online softmax update
        #pragma unroll
        for (int i = 0; i < 4; i++) {
            #pragma unroll
            for (int j = 0; j < 4; j++) s[i][j] *= 0.125f;  // 1/sqrt(64)
            float mx = fmaxf(fmaxf(s[i][0], s[i][1]), fmaxf(s[i][2], s[i][3]));
            #pragma unroll
            for (int off = 8; off >= 1; off >>= 1)
                mx = fmaxf(mx, __shfl_xor_sync(0xffffffffu, mx, off));
            const float mnew  = fmaxf(m_i[i], mx);
            const float alpha = __expf(m_i[i] - mnew);
            m_i[i] = mnew;
            float rs = 0.0f;
            #pragma unroll
            for (int j = 0; j < 4; j++) {
                s[i][j] = __expf(s[i][j] - mnew);
                rs += s[i][j];
            }
            #pragma unroll
            for (int off = 8; off >= 1; off >>= 1)
                rs += __shfl_xor_sync(0xffffffffu, rs, off);
            l_i[i] = l_i[i] * alpha + rs;
            #pragma unroll
            for (int j = 0; j < 4; j++) acc[i][j] *= alpha;
        }
        __syncthreads();   // all phase-1 reads of Kt done before overwrite as Pt

        // ---- write P transposed into Kt alias: Pt[key][row]
        #pragma unroll
        for (int i = 0; i < 4; i++)
            #pragma unroll
            for (int j = 0; j < 4; j++)
                Kt[SWZ(tx * 4 + j, ty * 4 + i)] = s[i][j];
        __syncthreads();

        // ---- phase 2: O += P V
        #pragma unroll 16
        for (int j = 0; j < 64; j++) {
            float pv[4], vv[4];
            *(float4*)pv = *(const float4*)&Kt[SWZ(j, ty * 4)];
            *(float4*)vv = *(const float4*)&Vs[j][tx * 4];
            #pragma unroll
            for (int i = 0; i < 4; i++)
                #pragma unroll
                for (int d2 = 0; d2 < 4; d2++)
                    acc[i][d2] = fmaf(pv[i], vv[d2], acc[i][d2]);
        }
    }

    // ---- epilogue: normalize, write ctx in [B,S,D] layout
    const int b = bh / NHEAD, h = bh % NHEAD;
    #pragma unroll
    for (int i = 0; i < 4; i++) {
        const int row = qb * 64 + ty * 4 + i;     // seq index
        const float inv = 1.0f / l_i[i];
        float4 o;
        o.x = acc[i][0] * inv; o.y = acc[i][1] * inv;
        o.z = acc[i][2] * inv; o.w = acc[i][3] * inv;
        float* out = g_ctx + ((size_t)(b * S_LEN + row)) * DMODEL + h * HDIM + tx * 4;
        *(float4*)out = o;
    }
}

// ---------------- launch ---------------------------------------------------
extern "C" void kernel_launch(void* const* d_in, const int* in_sizes, int n_in,
                              void* d_out, int out_size)
{
    const float* x  = (const float*)d_in[0];
    const float* wq = (const float*)d_in[1];
    const float* bq = (const float*)d_in[2];
    const float* wk = (const float*)d_in[3];
    const float* bk = (const float*)d_in[4];
    const float* wv = (const float*)d_in[5];
    const float* bv = (const float*)d_in[6];
    const float* wo = (const float*)d_in[7];
    const float* bo = (const float*)d_in[8];
    float* out = (float*)d_out;

    dim3 gq(DMODEL / 128, MTOT / 128, 3);
    gemm_qkv_kernel<<<gq, 256>>>(x, wq, bq, wk, bk, wv, bv);

    dim3 ga(S_LEN / 64, BATCH * NHEAD);
    flash_attn_kernel<<<ga, 256>>>();

    dim3 go(DMODEL / 128, MTOT / 128);
    gemm_out_kernel<<<go, 256>>>(wo, bo, out);
}

// round 2
// speedup vs baseline: 2.7333x; 2.7333x over previous
#include <cuda_runtime.h>
#include <cstdint>

#define S_LEN  2048
#define DMODEL 1024
#define NHEAD  16
#define HDIM   64
#define MTOT   4096

// ---------------- scratch (allocation-free: device globals) ----------------
__device__ float g_q[(size_t)MTOT * DMODEL];   // [B,H,S,Hd]
__device__ float g_k[(size_t)MTOT * DMODEL];
__device__ float g_v[(size_t)MTOT * DMODEL];
__device__ float g_ctx[(size_t)MTOT * DMODEL]; // [B,S,D]

// ---------------- tf32 helpers ---------------------------------------------
__device__ __forceinline__ float rtf(float x) {            // round-to-nearest tf32
    uint32_t u;
    asm("cvt.rna.tf32.f32 %0, %1;" : "=r"(u) : "f"(x));
    return __uint_as_float(u);
}
__device__ __forceinline__ uint32_t f2u(float x) { return __float_as_uint(x); }

__device__ __forceinline__ void ldsm4(uint32_t& r0, uint32_t& r1, uint32_t& r2, uint32_t& r3,
                                      uint32_t addr) {
    asm volatile("ldmatrix.sync.aligned.m8n8.x4.shared.b16 {%0,%1,%2,%3}, [%4];"
                 : "=r"(r0), "=r"(r1), "=r"(r2), "=r"(r3) : "r"(addr));
}
__device__ __forceinline__ void mma8(float* c, const uint32_t* a, uint32_t b0, uint32_t b1) {
    asm volatile("mma.sync.aligned.m16n8k8.row.col.f32.tf32.tf32.f32 "
                 "{%0,%1,%2,%3},{%4,%5,%6,%7},{%8,%9},{%0,%1,%2,%3};"
                 : "+f"(c[0]), "+f"(c[1]), "+f"(c[2]), "+f"(c[3])
                 : "r"(a[0]), "r"(a[1]), "r"(a[2]), "r"(a[3]), "r"(b0), "r"(b1));
}

// ---------------- tf32 GEMM: 128x128 CTA, BK=16, 8 warps (64x32 each) ------
template<bool SPLIT>
__device__ __forceinline__ void gemm_tf32(const float* __restrict__ A,
                                          const float* __restrict__ W,
                                          const float* __restrict__ bias,
                                          float* __restrict__ C)
{
    constexpr int LDA = 20;   // pad: conflict-free ldmatrix (5m+k4 mod 8 perm)
    constexpr int LDB = 132;
    __shared__ float As[2][128 * LDA];
    __shared__ float Bs[2][16 * LDB];

    const int tid = threadIdx.x, lt = tid & 31, wid = tid >> 5;
    const int wm = wid >> 2, wn = wid & 3;            // 2 x 4 warp grid
    const int m0 = blockIdx.y * 128, n0 = blockIdx.x * 128;

    const int arow = tid >> 1, acol = (tid & 1) * 8;  // A gmem->smem mapping
    const int krow = tid >> 4, ncol = (tid & 15) * 8; // B gmem->smem mapping

    // A-fragment ldmatrix lane mapping
    const int a_r  = (lt & 7) + ((lt >> 3) & 1) * 8;
    const int a_kg = (lt >> 4) * 4;

    const uint32_t sA = (uint32_t)__cvta_generic_to_shared(&As[0][0]);

    float acc[4][4][4];
    #pragma unroll
    for (int mi = 0; mi < 4; mi++)
        #pragma unroll
        for (int ni = 0; ni < 4; ni++)
            #pragma unroll
            for (int r = 0; r < 4; r++) acc[mi][ni][r] = 0.0f;

    const float* Ap = A + (size_t)(m0 + arow) * DMODEL + acol;
    const float* Wp = W + (size_t)krow * DMODEL + n0 + ncol;

    float4 av0, av1, bv0, bv1;
    // prologue: tile 0
    av0 = *(const float4*)(Ap);     av1 = *(const float4*)(Ap + 4);
    bv0 = *(const float4*)(Wp);     bv1 = *(const float4*)(Wp + 4);
    {
        float* as = &As[0][arow * LDA + acol];
        as[0] = rtf(av0.x); as[1] = rtf(av0.y); as[2] = rtf(av0.z); as[3] = rtf(av0.w);
        as[4] = rtf(av1.x); as[5] = rtf(av1.y); as[6] = rtf(av1.z); as[7] = rtf(av1.w);
        float* bs = &Bs[0][krow * LDB + ncol];
        bs[0] = rtf(bv0.x); bs[1] = rtf(bv0.y); bs[2] = rtf(bv0.z); bs[3] = rtf(bv0.w);
        bs[4] = rtf(bv1.x); bs[5] = rtf(bv1.y); bs[6] = rtf(bv1.z); bs[7] = rtf(bv1.w);
    }
    __syncthreads();

    for (int kt = 0; kt < 64; kt++) {
        const int buf = kt & 1;
        if (kt < 63) {
            const float* ap = Ap + (kt + 1) * 16;
            av0 = *(const float4*)(ap);  av1 = *(const float4*)(ap + 4);
            const float* wp = Wp + (size_t)(kt + 1) * 16 * DMODEL;
            bv0 = *(const float4*)(wp);  bv1 = *(const float4*)(wp + 4);
        }
        // compute on smem[buf]
        #pragma unroll
        for (int ks = 0; ks < 2; ks++) {
            uint32_t af[4][4];
            #pragma unroll
            for (int mi = 0; mi < 4; mi++) {
                uint32_t addr = sA + (uint32_t)((buf * 128 * LDA +
                                (wm * 64 + mi * 16 + a_r) * LDA + ks * 8 + a_kg) * 4);
                ldsm4(af[mi][0], af[mi][1], af[mi][2], af[mi][3], addr);
            }
            #pragma unroll
            for (int ni = 0; ni < 4; ni++) {
                const int bn = wn * 32 + ni * 8 + (lt >> 2);
                const int bk = ks * 8 + (lt & 3);
                uint32_t b0 = f2u(Bs[buf][bk * LDB + bn]);
                uint32_t b1 = f2u(Bs[buf][(bk + 4) * LDB + bn]);
                #pragma unroll
                for (int mi = 0; mi < 4; mi++) mma8(acc[mi][ni], af[mi], b0, b1);
            }
        }
        if (kt < 63) {
            float* as = &As[buf ^ 1][arow * LDA + acol];
            as[0] = rtf(av0.x); as[1] = rtf(av0.y); as[2] = rtf(av0.z); as[3] = rtf(av0.w);
            as[4] = rtf(av1.x); as[5] = rtf(av1.y); as[6] = rtf(av1.z); as[7] = rtf(av1.w);
            float* bs = &Bs[buf ^ 1][krow * LDB + ncol];
            bs[0] = rtf(bv0.x); bs[1] = rtf(bv0.y); bs[2] = rtf(bv0.z); bs[3] = rtf(bv0.w);
            bs[4] = rtf(bv1.x); bs[5] = rtf(bv1.y); bs[6] = rtf(bv1.z); bs[7] = rtf(bv1.w);
            __syncthreads();
        }
    }

    // epilogue: bias add + store
    #pragma unroll
    for (int mi = 0; mi < 4; mi++) {
        const int r0 = m0 + wm * 64 + mi * 16 + (lt >> 2);
        #pragma unroll
        for (int ni = 0; ni < 4; ni++) {
            const int cn = n0 + wn * 32 + ni * 8 + (lt & 3) * 2;
            const float bb0 = bias[cn], bb1 = bias[cn + 1];
            float o00 = acc[mi][ni][0] + bb0, o01 = acc[mi][ni][1] + bb1;
            float o10 = acc[mi][ni][2] + bb0, o11 = acc[mi][ni][3] + bb1;
            if (SPLIT) {
                const int b = r0 / S_LEN;
                const int h = cn >> 6, hd = cn & 63;
                {
                    const int s = r0 % S_LEN;
                    float* o = C + (((size_t)(b * NHEAD + h) * S_LEN + s) * HDIM + hd);
                    o[0] = o00; o[1] = o01;
                }
                {
                    const int s = (r0 + 8) % S_LEN;   // +8 stays in same batch (128-row tile)
                    float* o = C + (((size_t)(b * NHEAD + h) * S_LEN + s) * HDIM + hd);
                    o[0] = o10; o[1] = o11;
                }
            } else {
                float* o = C + (size_t)r0 * DMODEL + cn;
                o[0] = o00; o[1] = o01;
                o = C + (size_t)(r0 + 8) * DMODEL + cn;
                o[0] = o10; o[1] = o11;
            }
        }
    }
}

__global__ void __launch_bounds__(256)
gemm_qkv_kernel(const float* __restrict__ x,
                const float* __restrict__ wq, const float* __restrict__ bq,
                const float* __restrict__ wk, const float* __restrict__ bk,
                const float* __restrict__ wv, const float* __restrict__ bv)
{
    const float* W; const float* bias; float* C;
    if (blockIdx.z == 0)      { W = wq; bias = bq; C = g_q; }
    else if (blockIdx.z == 1) { W = wk; bias = bk; C = g_k; }
    else                      { W = wv; bias = bv; C = g_v; }
    gemm_tf32<true>(x, W, bias, C);
}

__global__ void __launch_bounds__(256)
gemm_out_kernel(const float* __restrict__ wo, const float* __restrict__ bo,
                float* __restrict__ out)
{
    gemm_tf32<false>(g_ctx, wo, bo, out);
}

// ---------------- flash attention, tf32 mma, 64q x 64k tiles ---------------
__global__ void __launch_bounds__(128)
flash_tf32_kernel(void)
{
    __shared__ float KP[64 * 68];   // K tile, aliased as P tile (and Q at start)
    __shared__ float Vs[64 * 68];   // V tile [key][d]

    const int tid = threadIdx.x, lt = tid & 31, wq = tid >> 5;
    const int qb = blockIdx.x, bh = blockIdx.y;

    const float* qbase = g_q + (size_t)bh * S_LEN * HDIM + (size_t)qb * 64 * HDIM;
    const float* kbase = g_k + (size_t)bh * S_LEN * HDIM;
    const float* vbase = g_v + (size_t)bh * S_LEN * HDIM;

    const uint32_t sKP = (uint32_t)__cvta_generic_to_shared(&KP[0]);
    // A-fragment lane mapping
    const int a_r  = (lt & 7) + ((lt >> 3) & 1) * 8;
    const int a_kg = (lt >> 4) * 4;
    // B-fragment (ldmatrix x4 = two n8 atoms) lane mapping
    const int b_r  = (lt & 7) + (lt >> 4) * 8;
    const int b_kg = ((lt >> 3) & 1) * 4;

    // ---- load Q (pre-scaled by 1/sqrt(Hd)), fragment into registers
    #pragma unroll
    for (int c = 0; c < 8; c++) {
        const int idx = c * 128 + tid;
        const int row = idx >> 4, d0 = (idx & 15) * 4;
        float4 q = *(const float4*)(qbase + row * HDIM + d0);
        KP[row * 68 + d0 + 0] = rtf(q.x * 0.125f);
        KP[row * 68 + d0 + 1] = rtf(q.y * 0.125f);
        KP[row * 68 + d0 + 2] = rtf(q.z * 0.125f);
        KP[row * 68 + d0 + 3] = rtf(q.w * 0.125f);
    }
    __syncthreads();
    uint32_t qf[8][4];
    #pragma unroll
    for (int ks = 0; ks < 8; ks++) {
        uint32_t addr = sKP + (uint32_t)(((wq * 16 + a_r) * 68 + ks * 8 + a_kg) * 4);
        ldsm4(qf[ks][0], qf[ks][1], qf[ks][2], qf[ks][3], addr);
    }

    float oacc[8][4];
    #pragma unroll
    for (int j = 0; j < 8; j++)
        #pragma unroll
        for (int r = 0; r < 4; r++) oacc[j][r] = 0.0f;
    float m0v = -1e30f, m1v = -1e30f, l0v = 0.0f, l1v = 0.0f;

    for (int kb = 0; kb < 32; kb++) {
        __syncthreads();   // previous-iter P/V reads (and initial Q frags) done
        #pragma unroll
        for (int c = 0; c < 8; c++) {
            const int idx = c * 128 + tid;
            const int key = idx >> 4, d0 = (idx & 15) * 4;
            const float* kp = kbase + (size_t)kb * 4096 + key * HDIM + d0;
            const float* vp = vbase + (size_t)kb * 4096 + key * HDIM + d0;
            float4 kv = *(const float4*)kp;
            float4 vv = *(const float4*)vp;
            KP[key * 68 + d0 + 0] = rtf(kv.x);
            KP[key * 68 + d0 + 1] = rtf(kv.y);
            KP[key * 68 + d0 + 2] = rtf(kv.z);
            KP[key * 68 + d0 + 3] = rtf(kv.w);
            Vs[key * 68 + d0 + 0] = rtf(vv.x);
            Vs[key * 68 + d0 + 1] = rtf(vv.y);
            Vs[key * 68 + d0 + 2] = rtf(vv.z);
            Vs[key * 68 + d0 + 3] = rtf(vv.w);
        }
        __syncthreads();

        // ---- S = Q K^T  (pre-scaled)
        float sacc[8][4];
        #pragma unroll
        for (int j = 0; j < 8; j++)
            #pragma unroll
            for (int r = 0; r < 4; r++) sacc[j][r] = 0.0f;

        #pragma unroll
        for (int ks = 0; ks < 8; ks++) {
            #pragma unroll
            for (int jj = 0; jj < 4; jj++) {
                uint32_t b0, b1, b2, b3;
                uint32_t addr = sKP + (uint32_t)(((jj * 16 + b_r) * 68 + ks * 8 + b_kg) * 4);
                ldsm4(b0, b1, b2, b3, addr);
                mma8(sacc[2 * jj],     qf[ks], b0, b1);
                mma8(sacc[2 * jj + 1], qf[ks], b2, b3);
            }
        }

        // ---- online softmax
        float mx0 = -1e30f, mx1 = -1e30f;
        #pragma unroll
        for (int j = 0; j < 8; j++) {
            mx0 = fmaxf(mx0, fmaxf(sacc[j][0], sacc[j][1]));
            mx1 = fmaxf(mx1, fmaxf(sacc[j][2], sacc[j][3]));
        }
        mx0 = fmaxf(mx0, __shfl_xor_sync(0xffffffffu, mx0, 1));
        mx0 = fmaxf(mx0, __shfl_xor_sync(0xffffffffu, mx0, 2));
        mx1 = fmaxf(mx1, __shfl_xor_sync(0xffffffffu, mx1, 1));
        mx1 = fmaxf(mx1, __shfl_xor_sync(0xffffffffu, mx1, 2));
        const float mn0 = fmaxf(m0v, mx0), mn1 = fmaxf(m1v, mx1);
        const float al0 = __expf(m0v - mn0), al1 = __expf(m1v - mn1);
        m0v = mn0; m1v = mn1;
        float s0 = 0.0f, s1 = 0.0f;
        #pragma unroll
        for (int j = 0; j < 8; j++) {
            sacc[j][0] = __expf(sacc[j][0] - mn0); s0 += sacc[j][0];
            sacc[j][1] = __expf(sacc[j][1] - mn0); s0 += sacc[j][1];
            sacc[j][2] = __expf(sacc[j][2] - mn1); s1 += sacc[j][2];
            sacc[j][3] = __expf(sacc[j][3] - mn1); s1 += sacc[j][3];
        }
        s0 += __shfl_xor_sync(0xffffffffu, s0, 1);
        s0 += __shfl_xor_sync(0xffffffffu, s0, 2);
        s1 += __shfl_xor_sync(0xffffffffu, s1, 1);
        s1 += __shfl_xor_sync(0xffffffffu, s1, 2);
        l0v = l0v * al0 + s0;
        l1v = l1v * al1 + s1;
        #pragma unroll
        for (int j = 0; j < 8; j++) {
            oacc[j][0] *= al0; oacc[j][1] *= al0;
            oacc[j][2] *= al1; oacc[j][3] *= al1;
        }

        __syncthreads();   // all warps finished reading K before overwriting as P

        // ---- store P (tf32-rounded) into KP
        const int pr = wq * 16 + (lt >> 2);
        #pragma unroll
        for (int j = 0; j < 8; j++) {
            const int pc = j * 8 + (lt & 3) * 2;
            KP[pr * 68 + pc]           = rtf(sacc[j][0]);
            KP[pr * 68 + pc + 1]       = rtf(sacc[j][1]);
            KP[(pr + 8) * 68 + pc]     = rtf(sacc[j][2]);
            KP[(pr + 8) * 68 + pc + 1] = rtf(sacc[j][3]);
        }
        __syncwarp();      // each warp reads only its own P rows

        // ---- O += P V
        #pragma unroll
        for (int ks = 0; ks < 8; ks++) {
            uint32_t pf[4];
            uint32_t addr = sKP + (uint32_t)(((wq * 16 + a_r) * 68 + ks * 8 + a_kg) * 4);
            ldsm4(pf[0], pf[1], pf[2], pf[3], addr);
            #pragma unroll
            for (int j = 0; j < 8; j++) {
                const int vk = ks * 8 + (lt & 3);
                const int vd = j * 8 + (lt >> 2);
                uint32_t b0 = f2u(Vs[vk * 68 + vd]);
                uint32_t b1 = f2u(Vs[(vk + 4) * 68 + vd]);
                mma8(oacc[j], pf, b0, b1);
            }
        }
    }

    // ---- epilogue: normalize + write [B,S,D]
    const int b = bh >> 4, h = bh & 15;
    const float inv0 = 1.0f / l0v, inv1 = 1.0f / l1v;
    const int r0g = qb * 64 + wq * 16 + (lt >> 2);
    #pragma unroll
    for (int j = 0; j < 8; j++) {
        const int d = j * 8 + (lt & 3) * 2;
        float* o0 = g_ctx + (size_t)(b * S_LEN + r0g) * DMODEL + h * HDIM + d;
        o0[0] = oacc[j][0] * inv0; o0[1] = oacc[j][1] * inv0;
        float* o1 = g_ctx + (size_t)(b * S_LEN + r0g + 8) * DMODEL + h * HDIM + d;
        o1[0] = oacc[j][2] * inv1; o1[1] = oacc[j][3] * inv1;
    }
}

// ---------------- launch ---------------------------------------------------
extern "C" void kernel_launch(void* const* d_in, const int* in_sizes, int n_in,
                              void* d_out, int out_size)
{
    const float* x  = (const float*)d_in[0];
    const float* wq = (const float*)d_in[1];
    const float* bq = (const float*)d_in[2];
    const float* wk = (const float*)d_in[3];
    const float* bk = (const float*)d_in[4];
    const float* wv = (const float*)d_in[5];
    const float* bv = (const float*)d_in[6];
    const float* wo = (const float*)d_in[7];
    const float* bo = (const float*)d_in[8];
    float* out = (float*)d_out;

    dim3 gq(DMODEL / 128, MTOT / 128, 3);
    gemm_qkv_kernel<<<gq, 256>>>(x, wq, bq, wk, bk, wv, bv);

    dim3 ga(S_LEN / 64, 2 * NHEAD);
    flash_tf32_kernel<<<ga, 128>>>();

    dim3 go(DMODEL / 128, MTOT / 128);
    gemm_out_kernel<<<go, 256>>>(wo, bo, out);
}

// round 6
// speedup vs baseline: 3.0377x; 1.1114x over previous
#include <cuda_runtime.h>
#include <cstdint>

#define S_LEN  2048
#define DMODEL 1024
#define NHEAD  16
#define HDIM   64
#define MTOT   4096

// ---------------- scratch (allocation-free: device globals) ----------------
__device__ float g_q[(size_t)MTOT * DMODEL];   // [B,H,S,Hd], tf32-rounded
__device__ float g_k[(size_t)MTOT * DMODEL];   // [B,H,S,Hd], tf32-rounded
__device__ float g_v[(size_t)MTOT * DMODEL];   // [B,H,S,Hd], tf32-rounded
__device__ float g_vt[(size_t)MTOT * DMODEL];  // [B,H,Hd,S], tf32-rounded
__device__ float g_ctx[(size_t)MTOT * DMODEL]; // [B,S,D],   tf32-rounded
__device__ float g_xr[(size_t)MTOT * DMODEL];  // tf32-rounded x
__device__ float g_wt[4][(size_t)DMODEL * DMODEL]; // W^T [n][k], tf32-rounded

// ---------------- helpers ----------------------------------------------------
__device__ __forceinline__ float rtf(float x) {
    uint32_t u;
    asm("cvt.rna.tf32.f32 %0, %1;" : "=r"(u) : "f"(x));
    return __uint_as_float(u);
}
__device__ __forceinline__ uint32_t sm_u32(const void* p) {
    uint32_t a;
    asm("{ .reg .u64 t; cvta.to.shared.u64 t, %1; cvt.u32.u64 %0, t; }" : "=r"(a) : "l"(p));
    return a;
}
#define CP16(dst, src) \
    asm volatile("cp.async.cg.shared.global [%0], [%1], 16;" :: "r"(dst), "l"(src))
#define CP_COMMIT() asm volatile("cp.async.commit_group;" ::: "memory")
#define CP_WAIT0()  asm volatile("cp.async.wait_group 0;" ::: "memory")
#define CP_WAIT1()  asm volatile("cp.async.wait_group 1;" ::: "memory")

__device__ __forceinline__ void ldsm4(uint32_t& r0, uint32_t& r1, uint32_t& r2, uint32_t& r3,
                                      uint32_t addr) {
    asm volatile("ldmatrix.sync.aligned.m8n8.x4.shared.b16 {%0,%1,%2,%3}, [%4];"
                 : "=r"(r0), "=r"(r1), "=r"(r2), "=r"(r3) : "r"(addr));
}
__device__ __forceinline__ void mma8(float* c, const uint32_t* a, uint32_t b0, uint32_t b1) {
    asm volatile("mma.sync.aligned.m16n8k8.row.col.f32.tf32.tf32.f32 "
                 "{%0,%1,%2,%3},{%4,%5,%6,%7},{%8,%9},{%0,%1,%2,%3};"
                 : "+f"(c[0]), "+f"(c[1]), "+f"(c[2]), "+f"(c[3])
                 : "r"(a[0]), "r"(a[1]), "r"(a[2]), "r"(a[3]), "r"(b0), "r"(b1));
}

// ---------------- pre-pass kernels ------------------------------------------
__global__ void __launch_bounds__(256)
round_x_kernel(const float* __restrict__ x)
{
    const float4* xi = (const float4*)x;
    float4* xo = (float4*)g_xr;
    const int n4 = MTOT * DMODEL / 4;
    for (int i = blockIdx.x * 256 + threadIdx.x; i < n4; i += gridDim.x * 256) {
        float4 v = xi[i];
        v.x = rtf(v.x); v.y = rtf(v.y); v.z = rtf(v.z); v.w = rtf(v.w);
        xo[i] = v;
    }
}

__global__ void __launch_bounds__(256)
transpose_w_kernel(const float* __restrict__ w0, const float* __restrict__ w1,
                   const float* __restrict__ w2, const float* __restrict__ w3)
{
    __shared__ float t[32][33];
    const int z = blockIdx.z;
    const float* w = (z == 0) ? w0 : (z == 1) ? w1 : (z == 2) ? w2 : w3;
    float* out = g_wt[z];
    const int tx = threadIdx.x, ty = threadIdx.y;
    const int n0 = blockIdx.x * 32, k0 = blockIdx.y * 32;
    #pragma unroll
    for (int i = 0; i < 4; i++)
        t[ty + i * 8][tx] = w[(size_t)(k0 + ty + i * 8) * DMODEL + n0 + tx];
    __syncthreads();
    #pragma unroll
    for (int i = 0; i < 4; i++)
        out[(size_t)(n0 + ty + i * 8) * DMODEL + k0 + tx] = rtf(t[tx][ty + i * 8]);
}

// V: [bh][s][hd] -> [bh][hd][s]   (values already tf32-rounded)
__global__ void __launch_bounds__(256)
transpose_v_kernel(void)
{
    __shared__ float t[32][33];
    const int bh = blockIdx.z;
    const float* src = g_v + (size_t)bh * S_LEN * HDIM;
    float* dst = g_vt + (size_t)bh * S_LEN * HDIM;
    const int tx = threadIdx.x, ty = threadIdx.y;
    const int s0 = blockIdx.x * 32, d0 = blockIdx.y * 32;
    #pragma unroll
    for (int i = 0; i < 4; i++)
        t[ty + i * 8][tx] = src[(size_t)(s0 + ty + i * 8) * HDIM + d0 + tx];
    __syncthreads();
    #pragma unroll
    for (int i = 0; i < 4; i++)
        dst[(size_t)(d0 + ty + i * 8) * S_LEN + s0 + tx] = t[tx][ty + i * 8];
}

// ---------------- tf32 GEMM via mma.sync: 128x128, BK=16, cp.async 3-stage --
// smem tiles: A[128][20] (rows m, 16 k-floats + pad4), B[128][20] (rows n).
// ldmatrix lane mapping (fp32-pair trick), identical for A and B fragments.
#define GLDA 20
#define GSTAGE (2 * 128 * GLDA * 4)        // 20480 B per stage (A+B)
#define GSMEM  (3 * GSTAGE)                // 61440 B

__device__ __forceinline__ void g_stage_load(uint32_t sbase, int s, int kt,
                                             const float* __restrict__ A,
                                             const float* __restrict__ Wt,
                                             int m0, int n0, int tid)
{
    const uint32_t ab = sbase + s * GSTAGE;
    const uint32_t bb = ab + 128 * GLDA * 4;
    #pragma unroll
    for (int i = 0; i < 2; i++) {          // A: 128 rows x 4 chunks = 512
        const int idx = i * 256 + tid;
        const int r = idx >> 2, c = idx & 3;
        CP16(ab + (uint32_t)(r * GLDA + c * 4) * 4,
             A + (size_t)(m0 + r) * DMODEL + kt * 16 + c * 4);
    }
    #pragma unroll
    for (int i = 0; i < 2; i++) {          // B: 128 rows x 4 chunks
        const int idx = i * 256 + tid;
        const int r = idx >> 2, c = idx & 3;
        CP16(bb + (uint32_t)(r * GLDA + c * 4) * 4,
             Wt + (size_t)(n0 + r) * DMODEL + kt * 16 + c * 4);
    }
}

template<bool SPLIT, bool RND>
__device__ __forceinline__ void gemm_body(const float* __restrict__ A,
                                          const float* __restrict__ Wt,
                                          const float* __restrict__ bias,
                                          float* __restrict__ C)
{
    extern __shared__ char smem[];
    const uint32_t sbase = sm_u32(smem);
    const int tid = threadIdx.x, lt = tid & 31, wid = tid >> 5;
    const int wm = wid >> 2, wn = wid & 3;          // 2x4 warps, 64x32 tiles
    const int m0 = blockIdx.y * 128, n0 = blockIdx.x * 128;
    const int a_r  = (lt & 7) + ((lt >> 3) & 1) * 8;
    const int a_kg = (lt >> 4) * 4;

    float acc[4][4][4];
    #pragma unroll
    for (int mi = 0; mi < 4; mi++)
        #pragma unroll
        for (int ni = 0; ni < 4; ni++)
            #pragma unroll
            for (int r = 0; r < 4; r++) acc[mi][ni][r] = 0.0f;

    g_stage_load(sbase, 0, 0, A, Wt, m0, n0, tid); CP_COMMIT();
    g_stage_load(sbase, 1, 1, A, Wt, m0, n0, tid); CP_COMMIT();

    for (int kt = 0; kt < 64; kt++) {
        const int s = kt % 3;
        if (kt == 63) CP_WAIT0(); else CP_WAIT1();
        __syncthreads();
        if (kt + 2 < 64) {
            g_stage_load(sbase, (kt + 2) % 3, kt + 2, A, Wt, m0, n0, tid);
            CP_COMMIT();
        }
        const uint32_t ab = sbase + s * GSTAGE;
        const uint32_t bb = ab + 128 * GLDA * 4;
        #pragma unroll
        for (int ks = 0; ks < 2; ks++) {
            uint32_t af[4][4], bf[2][4];
            #pragma unroll
            for (int mi = 0; mi < 4; mi++)
                ldsm4(af[mi][0], af[mi][1], af[mi][2], af[mi][3],
                      ab + (uint32_t)((wm * 64 + mi * 16 + a_r) * GLDA + ks * 8 + a_kg) * 4);
            #pragma unroll
            for (int ng = 0; ng < 2; ng++)
                ldsm4(bf[ng][0], bf[ng][1], bf[ng][2], bf[ng][3],
                      bb + (uint32_t)((wn * 32 + ng * 16 + a_r) * GLDA + ks * 8 + a_kg) * 4);
            #pragma unroll
            for (int ni = 0; ni < 4; ni++) {
                const int ng = ni >> 1;
                const uint32_t b0 = (ni & 1) ? bf[ng][1] : bf[ng][0];
                const uint32_t b1 = (ni & 1) ? bf[ng][3] : bf[ng][2];
                #pragma unroll
                for (int mi = 0; mi < 4; mi++) mma8(acc[mi][ni], af[mi], b0, b1);
            }
        }
    }

    // epilogue
    #pragma unroll
    for (int mi = 0; mi < 4; mi++) {
        const int r0 = m0 + wm * 64 + mi * 16 + (lt >> 2);
        #pragma unroll
        for (int ni = 0; ni < 4; ni++) {
            const int cn = n0 + wn * 32 + ni * 8 + (lt & 3) * 2;
            const float bb0 = bias[cn], bb1 = bias[cn + 1];
            float o00 = acc[mi][ni][0] + bb0, o01 = acc[mi][ni][1] + bb1;
            float o10 = acc[mi][ni][2] + bb0, o11 = acc[mi][ni][3] + bb1;
            if (RND) { o00 = rtf(o00); o01 = rtf(o01); o10 = rtf(o10); o11 = rtf(o11); }
            if (SPLIT) {
                const int b = r0 >> 11;
                const int h = cn >> 6, hd = cn & 63;
                const int s0 = r0 & 2047;
                float* o = C + (((size_t)(b * NHEAD + h) * S_LEN + s0) * HDIM + hd);
                o[0] = o00; o[1] = o01;
                o = C + (((size_t)(b * NHEAD + h) * S_LEN + s0 + 8) * HDIM + hd);
                o[0] = o10; o[1] = o11;
            } else {
                float* o = C + (size_t)r0 * DMODEL + cn;
                o[0] = o00; o[1] = o01;
                o = C + (size_t)(r0 + 8) * DMODEL + cn;
                o[0] = o10; o[1] = o11;
            }
        }
    }
}

__global__ void __launch_bounds__(256)
gemm_qkv_kernel(const float* __restrict__ bq, const float* __restrict__ bk,
                const float* __restrict__ bv)
{
    const float* bias; float* C; const float* Wt;
    if (blockIdx.z == 0)      { Wt = g_wt[0]; bias = bq; C = g_q; }
    else if (blockIdx.z == 1) { Wt = g_wt[1]; bias = bk; C = g_k; }
    else                      { Wt = g_wt[2]; bias = bv; C = g_v; }
    gemm_body<true, true>(g_xr, Wt, bias, C);
}

__global__ void __launch_bounds__(256)
gemm_out_kernel(const float* __restrict__ bo, float* __restrict__ out)
{
    gemm_body<false, false>(g_ctx, g_wt[3], bo, out);
}

// ---------------- flash attention: 128q x 64k tiles, 256 threads ------------
// smem (floats, stride 68): Qs[128][68] (aliased as P), K[2][64][68], Vt[2][64][68]
#define FLD 68
#define F_QS   0
#define F_K(b) (128 * FLD + (b) * 64 * FLD)
#define F_V(b) (128 * FLD + 2 * 64 * FLD + (b) * 64 * FLD)
#define FSMEM  ((128 * FLD + 4 * 64 * FLD) * 4)   // 104448 B

__device__ __forceinline__ void f_kv_load(uint32_t sbase, int buf, int kb,
                                          const float* __restrict__ kbase,
                                          const float* __restrict__ vtbase, int tid)
{
    const uint32_t kdst = sbase + F_K(buf) * 4;
    const uint32_t vdst = sbase + F_V(buf) * 4;
    #pragma unroll
    for (int i = 0; i < 4; i++) {          // K: 64 rows x 16 chunks
        const int idx = i * 256 + tid;
        const int r = idx >> 4, c = idx & 15;
        CP16(kdst + (uint32_t)(r * FLD + c * 4) * 4,
             kbase + (size_t)(kb * 64 + r) * HDIM + c * 4);
    }
    #pragma unroll
    for (int i = 0; i < 4; i++) {          // Vt: 64 d-rows x 16 chunks
        const int idx = i * 256 + tid;
        const int r = idx >> 4, c = idx & 15;
        CP16(vdst + (uint32_t)(r * FLD + c * 4) * 4,
             vtbase + (size_t)r * S_LEN + kb * 64 + c * 4);
    }
}

__global__ void __launch_bounds__(256)
flash_kernel(void)
{
    extern __shared__ char smem[];
    const uint32_t sbase = sm_u32(smem);
    float* sf = (float*)smem;

    const int tid = threadIdx.x, lt = tid & 31, wq = tid >> 5;
    const int qb = blockIdx.x, bh = blockIdx.y;

    const float* qbase  = g_q  + (size_t)bh * S_LEN * HDIM + (size_t)qb * 128 * HDIM;
    const float* kbase  = g_k  + (size_t)bh * S_LEN * HDIM;
    const float* vtbase = g_vt + (size_t)bh * S_LEN * HDIM;

    const int a_r  = (lt & 7) + ((lt >> 3) & 1) * 8;
    const int a_kg = (lt >> 4) * 4;

    // ---- load Q tile (group 0), then KV0 (group 1)
    #pragma unroll
    for (int i = 0; i < 8; i++) {          // Q: 128 rows x 16 chunks
        const int idx = i * 256 + tid;
        const int r = idx >> 4, c = idx & 15;
        CP16(sbase + (uint32_t)(F_QS + r * FLD + c * 4) * 4,
             qbase + (size_t)r * HDIM + c * 4);
    }
    CP_COMMIT();
    f_kv_load(sbase, 0, 0, kbase, vtbase, tid);
    CP_COMMIT();
    CP_WAIT1();            // Q done; KV0 may still fly
    __syncthreads();

    uint32_t qf[8][4];
    #pragma unroll
    for (int ks = 0; ks < 8; ks++)
        ldsm4(qf[ks][0], qf[ks][1], qf[ks][2], qf[ks][3],
              sbase + (uint32_t)((F_QS + (wq * 16 + a_r) * FLD + ks * 8 + a_kg)) * 4);

    float oacc[8][4];
    #pragma unroll
    for (int j = 0; j < 8; j++)
        #pragma unroll
        for (int r = 0; r < 4; r++) oacc[j][r] = 0.0f;
    float m0v = -1e30f, m1v = -1e30f, l0v = 0.0f, l1v = 0.0f;

    for (int kb = 0; kb < 32; kb++) {
        const int buf = kb & 1;
        CP_WAIT0();
        __syncthreads();
        if (kb + 1 < 32) {
            f_kv_load(sbase, buf ^ 1, kb + 1, kbase, vtbase, tid);
            CP_COMMIT();
        }

        // ---- phase 1: S = Q K^T
        float sacc[8][4];
        #pragma unroll
        for (int j = 0; j < 8; j++)
            #pragma unroll
            for (int r = 0; r < 4; r++) sacc[j][r] = 0.0f;
        const uint32_t kbuf = sbase + (uint32_t)F_K(buf) * 4;
        #pragma unroll
        for (int ks = 0; ks < 8; ks++) {
            #pragma unroll
            for (int kg = 0; kg < 4; kg++) {
                uint32_t b0, b1, b2, b3;
                ldsm4(b0, b1, b2, b3,
                      kbuf + (uint32_t)((kg * 16 + a_r) * FLD + ks * 8 + a_kg) * 4);
                mma8(sacc[kg * 2],     qf[ks], b0, b2);
                mma8(sacc[kg * 2 + 1], qf[ks], b1, b3);
            }
        }

        // ---- online softmax (scale 1/8 applied here; exact pow2)
        float mx0 = -1e30f, mx1 = -1e30f;
        #pragma unroll
        for (int j = 0; j < 8; j++) {
            sacc[j][0] *= 0.125f; sacc[j][1] *= 0.125f;
            sacc[j][2] *= 0.125f; sacc[j][3] *= 0.125f;
            mx0 = fmaxf(mx0, fmaxf(sacc[j][0], sacc[j][1]));
            mx1 = fmaxf(mx1, fmaxf(sacc[j][2], sacc[j][3]));
        }
        mx0 = fmaxf(mx0, __shfl_xor_sync(0xffffffffu, mx0, 1));
        mx0 = fmaxf(mx0, __shfl_xor_sync(0xffffffffu, mx0, 2));
        mx1 = fmaxf(mx1, __shfl_xor_sync(0xffffffffu, mx1, 1));
        mx1 = fmaxf(mx1, __shfl_xor_sync(0xffffffffu, mx1, 2));
        const float mn0 = fmaxf(m0v, mx0), mn1 = fmaxf(m1v, mx1);
        const float al0 = __expf(m0v - mn0), al1 = __expf(m1v - mn1);
        m0v = mn0; m1v = mn1;
        float s0 = 0.0f, s1 = 0.0f;
        #pragma unroll
        for (int j = 0; j < 8; j++) {
            sacc[j][0] = __expf(sacc[j][0] - mn0); s0 += sacc[j][0];
            sacc[j][1] = __expf(sacc[j][1] - mn0); s0 += sacc[j][1];
            sacc[j][2] = __expf(sacc[j][2] - mn1); s1 += sacc[j][2];
            sacc[j][3] = __expf(sacc[j][3] - mn1); s1 += sacc[j][3];
        }
        s0 += __shfl_xor_sync(0xffffffffu, s0, 1);
        s0 += __shfl_xor_sync(0xffffffffu, s0, 2);
        s1 += __shfl_xor_sync(0xffffffffu, s1, 1);
        s1 += __shfl_xor_sync(0xffffffffu, s1, 2);
        l0v = l0v * al0 + s0;
        l1v = l1v * al1 + s1;
        #pragma unroll
        for (int j = 0; j < 8; j++) {
            oacc[j][0] *= al0; oacc[j][1] *= al0;
            oacc[j][2] *= al1; oacc[j][3] *= al1;
        }

        // ---- store P into Qs alias (warp-private rows)
        const int pr = wq * 16 + (lt >> 2);
        #pragma unroll
        for (int j = 0; j < 8; j++) {
            const int pc = j * 8 + (lt & 3) * 2;
            sf[F_QS + pr * FLD + pc]           = rtf(sacc[j][0]);
            sf[F_QS + pr * FLD + pc + 1]       = rtf(sacc[j][1]);
            sf[F_QS + (pr + 8) * FLD + pc]     = rtf(sacc[j][2]);
            sf[F_QS + (pr + 8) * FLD + pc + 1] = rtf(sacc[j][3]);
        }
        __syncwarp();

        // ---- phase 2: O += P V   (V frags via ldmatrix on [d][key] tiles)
        const uint32_t vbuf = sbase + (uint32_t)F_V(buf) * 4;
        #pragma unroll
        for (int ks = 0; ks < 8; ks++) {
            uint32_t pf[4];
            ldsm4(pf[0], pf[1], pf[2], pf[3],
                  sbase + (uint32_t)((F_QS + (wq * 16 + a_r) * FLD + ks * 8 + a_kg)) * 4);
            #pragma unroll
            for (int dg = 0; dg < 4; dg++) {
                uint32_t v0, v1, v2, v3;
                ldsm4(v0, v1, v2, v3,
                      vbuf + (uint32_t)((dg * 16 + a_r) * FLD + ks * 8 + a_kg) * 4);
                mma8(oacc[dg * 2],     pf, v0, v2);
                mma8(oacc[dg * 2 + 1], pf, v1, v3);
            }
        }
    }

    // ---- epilogue: normalize + write [B,S,D], rounded for out-proj cp.async
    const int b = bh >> 4, h = bh & 15;
    const float inv0 = 1.0f / l0v, inv1 = 1.0f / l1v;
    const int r0g = qb * 128 + wq * 16 + (lt >> 2);
    #pragma unroll
    for (int j = 0; j < 8; j++) {
        const int d = j * 8 + (lt & 3) * 2;
        float* o0 = g_ctx + (size_t)(b * S_LEN + r0g) * DMODEL + h * HDIM + d;
        o0[0] = rtf(oacc[j][0] * inv0); o0[1] = rtf(oacc[j][1] * inv0);
        float* o1 = g_ctx + (size_t)(b * S_LEN + r0g + 8) * DMODEL + h * HDIM + d;
        o1[0] = rtf(oacc[j][2] * inv1); o1[1] = rtf(oacc[j][3] * inv1);
    }
}

// ---------------- launch ----------------------------------------------------
extern "C" void kernel_launch(void* const* d_in, const int* in_sizes, int n_in,
                              void* d_out, int out_size)
{
    const float* x  = (const float*)d_in[0];
    const float* wq = (const float*)d_in[1];
    const float* bq = (const float*)d_in[2];
    const float* wk = (const float*)d_in[3];
    const float* bk = (const float*)d_in[4];
    const float* wv = (const float*)d_in[5];
    const float* bv = (const float*)d_in[6];
    const float* wo = (const float*)d_in[7];
    const float* bo = (const float*)d_in[8];
    float* out = (float*)d_out;

    cudaFuncSetAttribute(gemm_qkv_kernel, cudaFuncAttributeMaxDynamicSharedMemorySize, GSMEM);
    cudaFuncSetAttribute(gemm_out_kernel, cudaFuncAttributeMaxDynamicSharedMemorySize, GSMEM);
    cudaFuncSetAttribute(flash_kernel,    cudaFuncAttributeMaxDynamicSharedMemorySize, FSMEM);

    round_x_kernel<<<1024, 256>>>(x);
    transpose_w_kernel<<<dim3(32, 32, 4), dim3(32, 8)>>>(wq, wk, wv, wo);

    dim3 gq(DMODEL / 128, MTOT / 128, 3);
    gemm_qkv_kernel<<<gq, 256, GSMEM>>>(bq, bk, bv);

    transpose_v_kernel<<<dim3(S_LEN / 32, HDIM / 32, 2 * NHEAD), dim3(32, 8)>>>();

    dim3 ga(S_LEN / 128, 2 * NHEAD);
    flash_kernel<<<ga, 256, FSMEM>>>();

    dim3 go(DMODEL / 128, MTOT / 128);
    gemm_out_kernel<<<go, 256, GSMEM>>>(bo, out);
}